// round 3
// baseline (speedup 1.0000x reference)
#include <cuda_runtime.h>

// Biquad (direct-form-II-transposed) over time, B=512 channels, T=48000.
//
// Parallelized as a blocked linear-recurrence scan:
//   s[n] = M s[n-1] + g x[n],  M = [[-a1, 1], [-a2, 0]]  (per-channel const)
// One block per channel. 500 chunks of 96 samples, one chunk per thread.
//   Pass A : zero-state recurrence per chunk -> y0 (in smem) + end state d_i
//   Scan   : e_i = P e_{i-1} + d_i with P = M^96 (powers of M commute ->
//            Hillis-Steele with per-level matrix Q, Q <- Q^2 each level)
//   Pass B : y[j] = y0[j] + (M^j s_in).z1   (1-FMA loop-carried chain)
// Whole channel staged in padded smem (stride 97 ~ 1 mod 32: conflict-free).

#define NCHAN   512
#define TLEN    48000
#define CHUNK   96
#define NCH     500          // chunks per channel = TLEN / CHUNK
#define STRIDE  97           // CHUNK + 1 pad (odd -> conflict-free strided LDS)
#define THREADS 512
#define SMEM_BYTES (NCH * STRIDE * 4 + THREADS * 8)

__global__ __launch_bounds__(THREADS, 1)
void biquad_scan_kernel(const float* __restrict__ x,
                        const float* __restrict__ gb0,
                        const float* __restrict__ gb1,
                        const float* __restrict__ gb2,
                        const float* __restrict__ ga1,
                        const float* __restrict__ ga2,
                        float* __restrict__ out)
{
    extern __shared__ float sx[];                       // NCH*STRIDE floats
    float2* sv = (float2*)(sx + NCH * STRIDE);          // per-chunk states

    const int c   = blockIdx.x;
    const int tid = threadIdx.x;

    const float B0 = gb0[c], B1 = gb1[c], B2 = gb2[c];
    const float A1 = ga1[c], A2 = ga2[c];

    // ---- Phase 1: coalesced load, padded layout addr = t + t/CHUNK ----
    const float* xc = x + (size_t)c * TLEN;
    #pragma unroll 4
    for (int t = tid; t < TLEN; t += THREADS)
        sx[t + t / CHUNK] = xc[t];
    __syncthreads();

    // ---- Phase 2: zero-state pass over own chunk; y0 written in place ----
    if (tid < NCH) {
        float* p = sx + tid * STRIDE;
        float z1 = 0.f, z2 = 0.f;
        #pragma unroll 4
        for (int j = 0; j < CHUNK; j++) {
            float xv = p[j];
            float y  = fmaf(B0, xv, z1);
            z1 = fmaf(-A1, y, fmaf(B1, xv, z2));
            z2 = fmaf(-A2, y, B2 * xv);
            p[j] = y;
        }
        sv[tid] = make_float2(z1, z2);
    }
    __syncthreads();

    // ---- P = M^CHUNK via repeated squaring (all threads, identical) ----
    // M  = [[-A1, 1], [-A2, 0]]
    // M2:
    float a00 = fmaf(-A1, -A1, -A2);   // A1^2 - A2
    float a01 = -A1;
    float a10 = A1 * A2;
    float a11 = -A2;
    // M3 = M2 * M:
    float q00 = fmaf(a00, -A1, -a01 * A2);
    float q01 = a00;
    float q10 = fmaf(a10, -A1, -a11 * A2);
    float q11 = a10;
    // (M3)^(2^5) = M^96:
    #pragma unroll
    for (int k = 0; k < 5; k++) {
        float t00 = fmaf(q00, q00, q01 * q10);
        float t01 = q01 * (q00 + q11);
        float t10 = q10 * (q00 + q11);
        float t11 = fmaf(q11, q11, q01 * q10);
        q00 = t00; q01 = t01; q10 = t10; q11 = t11;
    }

    // ---- Phase 3: Hillis-Steele affine scan over chunk end-states ----
    // After the scan, sv[i] = e_i = sum_{j<=i} P^{i-j} d_j  (true end state).
    for (int o = 1; o < THREADS; o <<= 1) {     // offsets 1..256 (9 levels)
        float2 cur, prv;
        const bool upd = (tid < NCH) && (tid >= o);
        if (upd) { cur = sv[tid]; prv = sv[tid - o]; }
        __syncthreads();
        if (upd) {
            cur.x = fmaf(q00, prv.x, fmaf(q01, prv.y, cur.x));
            cur.y = fmaf(q10, prv.x, fmaf(q11, prv.y, cur.y));
            sv[tid] = cur;
        }
        __syncthreads();
        float t00 = fmaf(q00, q00, q01 * q10);  // Q <- Q^2
        float t01 = q01 * (q00 + q11);
        float t10 = q10 * (q00 + q11);
        float t11 = fmaf(q11, q11, q01 * q10);
        q00 = t00; q01 = t01; q10 = t10; q11 = t11;
    }

    // ---- Phase 4: homogeneous correction  y[j] += (M^j s_in).z1 ----
    if (tid < NCH) {
        float mx = 0.f, my = 0.f;
        if (tid > 0) { float2 s = sv[tid - 1]; mx = s.x; my = s.y; }
        float* p = sx + tid * STRIDE;
        #pragma unroll 4
        for (int j = 0; j < CHUNK; j++) {
            p[j] += mx;
            float nmx = fmaf(-A1, mx, my);
            my = -A2 * mx;
            mx = nmx;
        }
    }
    __syncthreads();

    // ---- Phase 5: coalesced store ----
    float* oc = out + (size_t)c * TLEN;
    #pragma unroll 4
    for (int t = tid; t < TLEN; t += THREADS)
        oc[t] = sx[t + t / CHUNK];
}

extern "C" void kernel_launch(void* const* d_in, const int* in_sizes, int n_in,
                              void* d_out, int out_size)
{
    const float* x  = (const float*)d_in[0];
    const float* b0 = (const float*)d_in[1];
    const float* b1 = (const float*)d_in[2];
    const float* b2 = (const float*)d_in[3];
    const float* a1 = (const float*)d_in[4];
    const float* a2 = (const float*)d_in[5];
    float* out = (float*)d_out;

    cudaFuncSetAttribute(biquad_scan_kernel,
                         cudaFuncAttributeMaxDynamicSharedMemorySize,
                         SMEM_BYTES);
    biquad_scan_kernel<<<NCHAN, THREADS, SMEM_BYTES>>>(x, b0, b1, b2, a1, a2, out);
}

// round 4
// speedup vs baseline: 1.2294x; 1.2294x over previous
#include <cuda_runtime.h>

// Biquad DF2T over time, B=512 channels, T=48000, fp32.
//
// s[n] = M s[n-1] + g x[n],  M = [[-a1,1],[-a2,0]] per-channel constant.
// Each channel split into 4 segments of 12000 samples -> 2048 blocks.
// Per block: 500 chunks of 24 samples (one per thread), blocked scan:
//   Pass A: zero-state recurrence per chunk -> y0 in smem + end state d_i
//   Scan  : Hillis-Steele affine scan with level matrix Q^(2^l), Q = M^24
//   Pass B: y[j] += z1-component of (M^(24*tid+j) * s_in_seg + scanned state)
// Cross-segment state via decoupled look-back (device globals, flag+state),
// flags zeroed by a tiny init kernel each launch (graph-capturable).
// ~54KB smem/CTA -> 3 CTAs/SM -> memory phases of co-resident CTAs overlap
// other CTAs' compute phases.

#define NCHAN   512
#define TLEN    48000
#define NSEG    4
#define SEG     12000
#define CHUNK   24
#define NCH     500           // chunks per segment
#define STRIDE  25            // CHUNK+1 (odd -> conflict-free strided LDS)
#define THREADS 512
#define NBLK    (NCHAN * NSEG)

#define SMEM_FLOATS (NCH * STRIDE)                         // 12500
#define SMEM_BYTES  (SMEM_FLOATS * 4 + THREADS * 8 + 16)   // ~54.1 KB

__device__ int    g_flag[NBLK];
__device__ float2 g_state[NBLK];

__global__ void init_flags_kernel() {
    int i = blockIdx.x * blockDim.x + threadIdx.x;
    if (i < NBLK) g_flag[i] = 0;
}

__global__ __launch_bounds__(THREADS, 3)
void biquad_lookback_kernel(const float* __restrict__ x,
                            const float* __restrict__ gb0,
                            const float* __restrict__ gb1,
                            const float* __restrict__ gb2,
                            const float* __restrict__ ga1,
                            const float* __restrict__ ga2,
                            float* __restrict__ out)
{
    extern __shared__ float sx[];                    // SMEM_FLOATS floats
    float2* sv      = (float2*)(sx + SMEM_FLOATS);   // THREADS states
    float2* s_in_sh = (float2*)(sv + THREADS);       // broadcast slot

    const int bid = blockIdx.x;
    const int c   = bid >> 2;
    const int seg = bid & 3;
    const int tid = threadIdx.x;

    const float B0 = gb0[c], B1 = gb1[c], B2 = gb2[c];
    const float A1 = ga1[c], A2 = ga2[c];

    // ---- Phase 1: coalesced load into padded layout (addr = t + t/24) ----
    const float* xc = x + (size_t)c * TLEN + seg * SEG;
    #pragma unroll 4
    for (int t = tid; t < SEG; t += THREADS)
        sx[t + t / CHUNK] = xc[t];
    __syncthreads();

    // ---- Phase 2: zero-state pass over own chunk, y0 written in place ----
    if (tid < NCH) {
        float* p = sx + tid * STRIDE;
        float z1 = 0.f, z2 = 0.f;
        #pragma unroll
        for (int j = 0; j < CHUNK; j++) {
            float xv = p[j];
            float y  = fmaf(B0, xv, z1);
            z1 = fmaf(-A1, y, fmaf(B1, xv, z2));
            z2 = fmaf(-A2, y, B2 * xv);
            p[j] = y;
        }
        sv[tid] = make_float2(z1, z2);
    }

    // ---- Q = M^24: M^2, M^3, then 3 squarings (3 * 2^3 = 24) ----
    float a00 = fmaf(-A1, -A1, -A2), a01 = -A1, a10 = A1 * A2, a11 = -A2; // M^2
    float q00 = fmaf(a00, -A1, -a01 * A2), q01 = a00,
          q10 = fmaf(a10, -A1, -a11 * A2), q11 = a10;                     // M^3
    #pragma unroll
    for (int k = 0; k < 3; k++) {
        float t00 = fmaf(q00, q00, q01 * q10), t01 = q01 * (q00 + q11),
              t10 = q10 * (q00 + q11),         t11 = fmaf(q11, q11, q01 * q10);
        q00 = t00; q01 = t01; q10 = t10; q11 = t11;
    }

    // ---- one squaring chain yields per-thread Q^tid (= M^(24*tid))
    //      and the uniform segment matrix P = Q^500 (= M^12000) ----
    float m00 = 1.f, m01 = 0.f, m10 = 0.f, m11 = 1.f;   // Q^tid
    float P00 = 1.f, P01 = 0.f, P10 = 0.f, P11 = 1.f;   // Q^500
    {
        float e00 = q00, e01 = q01, e10 = q10, e11 = q11;
        const int tb = (tid < NCH) ? tid : 0;
        #pragma unroll
        for (int k = 0; k < 9; k++) {
            if ((tb >> k) & 1) {
                float r00 = fmaf(e00, m00, e01 * m10), r01 = fmaf(e00, m01, e01 * m11),
                      r10 = fmaf(e10, m00, e11 * m10), r11 = fmaf(e10, m01, e11 * m11);
                m00 = r00; m01 = r01; m10 = r10; m11 = r11;
            }
            if ((500 >> k) & 1) {
                float r00 = fmaf(e00, P00, e01 * P10), r01 = fmaf(e00, P01, e01 * P11),
                      r10 = fmaf(e10, P00, e11 * P10), r11 = fmaf(e10, P01, e11 * P11);
                P00 = r00; P01 = r01; P10 = r10; P11 = r11;
            }
            float t00 = fmaf(e00, e00, e01 * e10), t01 = e01 * (e00 + e11),
                  t10 = e10 * (e00 + e11),         t11 = fmaf(e11, e11, e01 * e10);
            e00 = t00; e01 = t01; e10 = t10; e11 = t11;
        }
    }
    __syncthreads();

    // ---- Phase 3: Hillis-Steele affine scan over chunk end-states ----
    {
        float l00 = q00, l01 = q01, l10 = q10, l11 = q11;
        for (int o = 1; o < THREADS; o <<= 1) {
            float2 cur, prv;
            const bool upd = (tid < NCH) && (tid >= o);
            if (upd) { cur = sv[tid]; prv = sv[tid - o]; }
            __syncthreads();
            if (upd) {
                cur.x = fmaf(l00, prv.x, fmaf(l01, prv.y, cur.x));
                cur.y = fmaf(l10, prv.x, fmaf(l11, prv.y, cur.y));
                sv[tid] = cur;
            }
            __syncthreads();
            float t00 = fmaf(l00, l00, l01 * l10), t01 = l01 * (l00 + l11),
                  t10 = l10 * (l00 + l11),         t11 = fmaf(l11, l11, l01 * l10);
            l00 = t00; l01 = t01; l10 = t10; l11 = t11;
        }
    }

    // ---- Look-back: chain segment states through device globals ----
    if (tid == 0) {
        float2 sin_ = make_float2(0.f, 0.f);
        if (seg > 0) {
            volatile int* fp = g_flag + (bid - 1);
            while (*fp == 0) { }
            __threadfence();
            volatile float* sp = (volatile float*)&g_state[bid - 1];
            sin_.x = sp[0]; sin_.y = sp[1];
        }
        if (seg < NSEG - 1) {
            float2 el = sv[NCH - 1];
            float2 inc;
            inc.x = fmaf(P00, sin_.x, fmaf(P01, sin_.y, el.x));
            inc.y = fmaf(P10, sin_.x, fmaf(P11, sin_.y, el.y));
            volatile float* dp = (volatile float*)&g_state[bid];
            dp[0] = inc.x; dp[1] = inc.y;
            __threadfence();
            *((volatile int*)(g_flag + bid)) = 1;
        }
        *s_in_sh = sin_;
    }
    __syncthreads();

    // ---- Phase 4: homogeneous correction, 1-FMA loop-carried chain ----
    if (tid < NCH) {
        float2 sin_ = *s_in_sh;
        float hx = fmaf(m00, sin_.x, m01 * sin_.y);   // M^(24*tid) * s_in
        float hy = fmaf(m10, sin_.x, m11 * sin_.y);
        if (tid > 0) { float2 s = sv[tid - 1]; hx += s.x; hy += s.y; }
        float* p = sx + tid * STRIDE;
        #pragma unroll
        for (int j = 0; j < CHUNK; j++) {
            p[j] += hx;
            float nx = fmaf(-A1, hx, hy);
            hy = -A2 * hx;
            hx = nx;
        }
    }
    __syncthreads();

    // ---- Phase 5: coalesced store ----
    float* oc = out + (size_t)c * TLEN + seg * SEG;
    #pragma unroll 4
    for (int t = tid; t < SEG; t += THREADS)
        oc[t] = sx[t + t / CHUNK];
}

extern "C" void kernel_launch(void* const* d_in, const int* in_sizes, int n_in,
                              void* d_out, int out_size)
{
    const float* x  = (const float*)d_in[0];
    const float* b0 = (const float*)d_in[1];
    const float* b1 = (const float*)d_in[2];
    const float* b2 = (const float*)d_in[3];
    const float* a1 = (const float*)d_in[4];
    const float* a2 = (const float*)d_in[5];
    float* out = (float*)d_out;

    cudaFuncSetAttribute(biquad_lookback_kernel,
                         cudaFuncAttributeMaxDynamicSharedMemorySize,
                         SMEM_BYTES);

    init_flags_kernel<<<NBLK / THREADS, THREADS>>>();
    biquad_lookback_kernel<<<NBLK, THREADS, SMEM_BYTES>>>(x, b0, b1, b2, a1, a2, out);
}

// round 5
// speedup vs baseline: 1.2862x; 1.0462x over previous
#include <cuda_runtime.h>

// Biquad DF2T, B=512 channels, T=48000, fp32.
// s[n] = M s[n-1] + g x[n],  M = [[-a1,1],[-a2,0]] per-channel constant.
//
// 4 segments/channel (2048 blocks, ~54KB smem -> 3 CTAs/SM). Per block:
// 500 chunks x 24 samples, one chunk per thread (512 threads).
//   passA : zero-state recurrence per chunk -> y0 in smem + end state d_i
//   scan  : shuffle-based two-level affine scan (Q = M^24 level matrices)
//   store : y = y0 + row0(M^j) . sv_in[chunk], fused into float4 STG
// Cross-segment state via decoupled look-back (device globals), done by
// thread 499 which holds e_499 in-register.

#define NCHAN   512
#define TLEN    48000
#define NSEG    4
#define SEG     12000
#define CHUNK   24
#define NCH     500
#define STRIDE  25          // CHUNK+1, odd -> conflict-free passA rows
#define THREADS 512
#define NBLK    (NCHAN * NSEG)
#define NF4     (SEG / 4)   // 3000 float4 per segment

struct SmemLayout {
    float  sx[NCH * STRIDE];   // staged samples / y0 (padded: addr = t + t/24)
    float2 sv_in[NCH];         // incoming state per chunk
    float2 warp_agg[16];
    float2 warp_E[16];
    float2 mj[CHUNK];          // row0 of M^j, j=0..23
    float2 s_in;               // segment incoming state (broadcast)
};
#define SMEM_BYTES ((int)sizeof(SmemLayout))

__device__ int    g_flag[NBLK];
__device__ float2 g_state[NBLK];

__global__ void init_flags_kernel() {
    int i = blockIdx.x * blockDim.x + threadIdx.x;
    if (i < NBLK) g_flag[i] = 0;
}

#define MATSQ(p00,p01,p10,p11) do {                                  \
    float _t00 = fmaf(p00, p00, p01 * p10);                          \
    float _t01 = p01 * (p00 + p11);                                  \
    float _t10 = p10 * (p00 + p11);                                  \
    float _t11 = fmaf(p11, p11, p01 * p10);                          \
    p00 = _t00; p01 = _t01; p10 = _t10; p11 = _t11; } while (0)

// m <- e * m
#define MATMUL_L(e00,e01,e10,e11, m00,m01,m10,m11) do {              \
    float _r00 = fmaf(e00, m00, e01 * m10);                          \
    float _r01 = fmaf(e00, m01, e01 * m11);                          \
    float _r10 = fmaf(e10, m00, e11 * m10);                          \
    float _r11 = fmaf(e10, m01, e11 * m11);                          \
    m00 = _r00; m01 = _r01; m10 = _r10; m11 = _r11; } while (0)

__global__ __launch_bounds__(THREADS, 3)
void biquad_kernel(const float* __restrict__ x,
                   const float* __restrict__ gb0,
                   const float* __restrict__ gb1,
                   const float* __restrict__ gb2,
                   const float* __restrict__ ga1,
                   const float* __restrict__ ga2,
                   float* __restrict__ out)
{
    extern __shared__ char smem_raw[];
    SmemLayout* S = (SmemLayout*)smem_raw;

    const int bid  = blockIdx.x;
    const int c    = bid >> 2;
    const int seg  = bid & 3;
    const int tid  = threadIdx.x;
    const int lane = tid & 31;
    const int warp = tid >> 5;

    const float A1 = ga1[c], A2 = ga2[c];
    const float B0 = gb0[c], B1 = gb1[c], B2 = gb2[c];

    // ---- load: float4 global -> padded smem ----
    const float4* xc4 = (const float4*)(x + (size_t)c * TLEN + (size_t)seg * SEG);
    for (int i = tid; i < NF4; i += THREADS) {
        float4 v = xc4[i];
        int ch = i / 6;                  // chunk = (4i)/24
        int j  = (i - ch * 6) << 2;
        float* p = S->sx + ch * STRIDE + j;
        p[0] = v.x; p[1] = v.y; p[2] = v.z; p[3] = v.w;
    }

    // ---- mj table: row0 of M^j for j = 0..23 (binary powering of M) ----
    if (tid < CHUNK) {
        float r00 = 1.f, r01 = 0.f, r10 = 0.f, r11 = 1.f;
        float e00 = -A1, e01 = 1.f, e10 = -A2, e11 = 0.f;
        #pragma unroll
        for (int k = 0; k < 5; k++) {
            if ((tid >> k) & 1) MATMUL_L(e00,e01,e10,e11, r00,r01,r10,r11);
            MATSQ(e00,e01,e10,e11);
        }
        S->mj[tid] = make_float2(r00, r01);
    }
    __syncthreads();                                        // B1

    // ---- passA: zero-state recurrence, y0 written in place ----
    float z1 = 0.f, z2 = 0.f;
    if (tid < NCH) {
        float* p = S->sx + tid * STRIDE;
        #pragma unroll
        for (int j = 0; j < CHUNK; j++) {
            float xv = p[j];
            float y  = fmaf(B0, xv, z1);
            float w  = fmaf(B1, xv, z2);
            z1 = fmaf(-A1, y, w);
            z2 = fmaf(-A2, y, B2 * xv);
            p[j] = y;
        }
    }

    // ---- Q = M^24 : M^2, M^3, then 3 squarings ----
    float a00 = fmaf(A1, A1, -A2), a01 = -A1, a10 = A1 * A2, a11 = -A2;  // M^2
    float q00 = fmaf(a00, -A1, -(a01 * A2)), q01 = a00,
          q10 = fmaf(a10, -A1, -(a11 * A2)), q11 = a10;                  // M^3
    #pragma unroll
    for (int k = 0; k < 3; k++) MATSQ(q00,q01,q10,q11);                  // M^24

    // ---- one chain: m = Q^tid, L = Q^lane (snapshot), P = Q^500 ----
    float m00=1.f,m01=0.f,m10=0.f,m11=1.f;
    float P00=1.f,P01=0.f,P10=0.f,P11=1.f;
    float L00,L01,L10,L11;
    {
        float e00=q00,e01=q01,e10=q10,e11=q11;
        #pragma unroll
        for (int k = 0; k < 9; k++) {
            if ((tid >> k) & 1) MATMUL_L(e00,e01,e10,e11, m00,m01,m10,m11);
            if ((500 >> k) & 1) MATMUL_L(e00,e01,e10,e11, P00,P01,P10,P11);
            if (k == 4) { L00=m00; L01=m01; L10=m10; L11=m11; }
            MATSQ(e00,e01,e10,e11);
        }
    }
    // g = Q^(lane+1) = Q * Q^lane
    float g00 = fmaf(q00, L00, q01 * L10), g01 = fmaf(q00, L01, q01 * L11);
    float g10 = fmaf(q10, L00, q11 * L10), g11 = fmaf(q10, L01, q11 * L11);

    // ---- in-warp inclusive affine scan (shuffles, level matrix Q^(2^l)) ----
    float ex = z1, ey = z2;
    float l00=q00,l01=q01,l10=q10,l11=q11;
    #pragma unroll
    for (int o = 1; o < 32; o <<= 1) {
        float px = __shfl_up_sync(0xffffffffu, ex, o);
        float py = __shfl_up_sync(0xffffffffu, ey, o);
        if (lane >= o) {
            ex = fmaf(l00, px, fmaf(l01, py, ex));
            ey = fmaf(l10, px, fmaf(l11, py, ey));
        }
        MATSQ(l00,l01,l10,l11);          // after loop: l = Q^32
    }
    if (lane == 31) S->warp_agg[warp] = make_float2(ex, ey);
    __syncthreads();                                        // B2

    // ---- cross-warp scan of 16 aggregates by warp 0 ----
    if (warp == 0) {
        float wx = 0.f, wy = 0.f;
        if (lane < 16) { float2 t = S->warp_agg[lane]; wx = t.x; wy = t.y; }
        float r00=l00,r01=l01,r10=l10,r11=l11;   // Q^32
        #pragma unroll
        for (int o = 1; o < 16; o <<= 1) {
            float px = __shfl_up_sync(0xffffffffu, wx, o);
            float py = __shfl_up_sync(0xffffffffu, wy, o);
            if (lane >= o && lane < 16) {
                wx = fmaf(r00, px, fmaf(r01, py, wx));
                wy = fmaf(r10, px, fmaf(r11, py, wy));
            }
            MATSQ(r00,r01,r10,r11);
        }
        if (lane < 16) S->warp_E[lane] = make_float2(wx, wy);
    }
    __syncthreads();                                        // B3

    // ---- apply cross-warp prefix: e_i = w_i + Q^(lane+1) * E_{warp-1} ----
    float Ex = 0.f, Ey = 0.f;
    if (warp > 0) { float2 t = S->warp_E[warp - 1]; Ex = t.x; Ey = t.y; }
    ex = fmaf(g00, Ex, fmaf(g01, Ey, ex));
    ey = fmaf(g10, Ex, fmaf(g11, Ey, ey));
    // previous element's inclusive state (e_{tid-1})
    float pex = __shfl_up_sync(0xffffffffu, ex, 1);
    float pey = __shfl_up_sync(0xffffffffu, ey, 1);
    if (lane == 0) { pex = Ex; pey = Ey; }       // tid==0 -> (0,0)

    // ---- look-back by thread 499 (holds e_499 = segment zero-state end) ----
    if (tid == NCH - 1) {
        float sinx = 0.f, siny = 0.f;
        if (seg > 0) {
            volatile int* fp = g_flag + (bid - 1);
            while (*fp == 0) { }
            __threadfence();
            volatile float* sp = (volatile float*)&g_state[bid - 1];
            sinx = sp[0]; siny = sp[1];
        }
        if (seg < NSEG - 1) {
            float ix = fmaf(P00, sinx, fmaf(P01, siny, ex));
            float iy = fmaf(P10, sinx, fmaf(P11, siny, ey));
            volatile float* dp = (volatile float*)&g_state[bid];
            dp[0] = ix; dp[1] = iy;
            __threadfence();
            *((volatile int*)(g_flag + bid)) = 1;
        }
        S->s_in = make_float2(sinx, siny);
    }
    __syncthreads();                                        // B4

    // ---- per-chunk incoming state: sv_in[t] = Q^t * s_in + e_{t-1} ----
    {
        float2 si = S->s_in;
        if (tid < NCH) {
            float hx = fmaf(m00, si.x, fmaf(m01, si.y, pex));
            float hy = fmaf(m10, si.x, fmaf(m11, si.y, pey));
            S->sv_in[tid] = make_float2(hx, hy);
        }
    }
    __syncthreads();                                        // B5

    // ---- store: y = y0 + row0(M^j) . sv_in[chunk], float4 STG ----
    float4* oc4 = (float4*)(out + (size_t)c * TLEN + (size_t)seg * SEG);
    for (int i = tid; i < NF4; i += THREADS) {
        int ch = i / 6;
        int j  = (i - ch * 6) << 2;
        float2 s  = S->sv_in[ch];
        const float* p = S->sx + ch * STRIDE + j;
        float2 r0 = S->mj[j],     r1 = S->mj[j + 1];
        float2 r2 = S->mj[j + 2], r3 = S->mj[j + 3];
        float4 v;
        v.x = fmaf(r0.x, s.x, fmaf(r0.y, s.y, p[0]));
        v.y = fmaf(r1.x, s.x, fmaf(r1.y, s.y, p[1]));
        v.z = fmaf(r2.x, s.x, fmaf(r2.y, s.y, p[2]));
        v.w = fmaf(r3.x, s.x, fmaf(r3.y, s.y, p[3]));
        oc4[i] = v;
    }
}

extern "C" void kernel_launch(void* const* d_in, const int* in_sizes, int n_in,
                              void* d_out, int out_size)
{
    const float* x  = (const float*)d_in[0];
    const float* b0 = (const float*)d_in[1];
    const float* b1 = (const float*)d_in[2];
    const float* b2 = (const float*)d_in[3];
    const float* a1 = (const float*)d_in[4];
    const float* a2 = (const float*)d_in[5];
    float* out = (float*)d_out;

    cudaFuncSetAttribute(biquad_kernel,
                         cudaFuncAttributeMaxDynamicSharedMemorySize,
                         SMEM_BYTES);

    init_flags_kernel<<<NBLK / THREADS, THREADS>>>();
    biquad_kernel<<<NBLK, THREADS, SMEM_BYTES>>>(x, b0, b1, b2, a1, a2, out);
}

// round 8
// speedup vs baseline: 1.4513x; 1.1283x over previous
#include <cuda_runtime.h>

// Biquad DF2T, B=512 channels, T=48000, fp32.
// s[n] = M s[n-1] + g x[n],  M = [[-a1,1],[-a2,0]] per-channel constant.
//
// 4 segments/channel (2048 blocks). 375 chunks x 32 samples per segment,
// one chunk per thread. Q = M^32.
//   passA : zero-state recurrence per chunk -> y0 in smem + end state d_i
//   scan  : shuffle two-level affine scan; thread 0 seeds with Q*s_in so the
//           scanned values ARE true states (no Q^tid / Q^500 chains needed)
//   store : y = y0 + row0(M^j) . sv_in[chunk], fused into float4 STG
// Cross-segment look-back: thread 0 spins for predecessor state pre-scan;
// thread NCH-1 publishes e'_{NCH-1} post-scan.
// ~53.5KB smem, 32 regs -> 4 CTAs/SM (2048 thr = SM max).

#define NCHAN   512
#define TLEN    48000
#define NSEG    4
#define SEG     12000
#define CHUNK   32
#define NCH     375
#define STRIDE  33          // CHUNK+1, odd -> conflict-free rows
#define THREADS 512
#define NBLK    (NCHAN * NSEG)
#define NF4     (SEG / 4)   // 3000

struct SmemLayout {
    float4 gt[32];             // Q^(lane+1), full 2x2 (m00,m01,m10,m11)
    float2 mj[CHUNK];          // row0 of M^j, j=0..31
    float2 sv_in[384];         // incoming state per chunk (NCH used)
    float2 warp_agg[16];
    float2 warp_E[16];
    float  sx[NCH * STRIDE];   // staged samples / y0 (addr = 33*ch + j)
};
#define SMEM_BYTES ((int)sizeof(SmemLayout))

__device__ int    g_flag[NBLK];
__device__ float2 g_state[NBLK];

__global__ void init_flags_kernel() {
    int i = blockIdx.x * blockDim.x + threadIdx.x;
    if (i < NBLK) g_flag[i] = 0;
}

#define MATSQ(p00,p01,p10,p11) do {                                  \
    float _t00 = fmaf(p00, p00, p01 * p10);                          \
    float _t01 = p01 * (p00 + p11);                                  \
    float _t10 = p10 * (p00 + p11);                                  \
    float _t11 = fmaf(p11, p11, p01 * p10);                          \
    p00 = _t00; p01 = _t01; p10 = _t10; p11 = _t11; } while (0)

// m <- e * m
#define MATMUL_L(e00,e01,e10,e11, m00,m01,m10,m11) do {              \
    float _r00 = fmaf(e00, m00, e01 * m10);                          \
    float _r01 = fmaf(e00, m01, e01 * m11);                          \
    float _r10 = fmaf(e10, m00, e11 * m10);                          \
    float _r11 = fmaf(e10, m01, e11 * m11);                          \
    m00 = _r00; m01 = _r01; m10 = _r10; m11 = _r11; } while (0)

__global__ __launch_bounds__(THREADS, 4)
void biquad_kernel(const float* __restrict__ x,
                   const float* __restrict__ gb0,
                   const float* __restrict__ gb1,
                   const float* __restrict__ gb2,
                   const float* __restrict__ ga1,
                   const float* __restrict__ ga2,
                   float* __restrict__ out)
{
    extern __shared__ char smem_raw[];
    SmemLayout* S = (SmemLayout*)smem_raw;

    const int bid  = blockIdx.x;
    const int c    = bid >> 2;
    const int seg  = bid & 3;
    const int tid  = threadIdx.x;
    const int lane = tid & 31;
    const int warp = tid >> 5;

    const float A1 = ga1[c], A2 = ga2[c];

    // ---- Q = M^32 : M^2, then 4 squarings ----
    float q00 = fmaf(A1, A1, -A2), q01 = -A1, q10 = A1 * A2, q11 = -A2;  // M^2
    #pragma unroll
    for (int k = 0; k < 4; k++) MATSQ(q00,q01,q10,q11);                  // M^32

    // ---- tables (parallel with load): mj by tid<32, gt by tid in [32,64) ----
    if (tid < 32) {                       // mj[tid] = row0 of M^tid
        float r00 = 1.f, r01 = 0.f, r10 = 0.f, r11 = 1.f;
        float e00 = -A1, e01 = 1.f, e10 = -A2, e11 = 0.f;
        #pragma unroll
        for (int k = 0; k < 5; k++) {
            if ((tid >> k) & 1) MATMUL_L(e00,e01,e10,e11, r00,r01,r10,r11);
            MATSQ(e00,e01,e10,e11);
        }
        S->mj[tid] = make_float2(r00, r01);
    } else if (tid < 64) {                // gt[tid-32] = Q^(tid-31)
        int n = tid - 31;                 // 1..32
        float r00 = 1.f, r01 = 0.f, r10 = 0.f, r11 = 1.f;
        float e00 = q00, e01 = q01, e10 = q10, e11 = q11;
        #pragma unroll
        for (int k = 0; k < 6; k++) {
            if ((n >> k) & 1) MATMUL_L(e00,e01,e10,e11, r00,r01,r10,r11);
            MATSQ(e00,e01,e10,e11);
        }
        S->gt[tid - 32] = make_float4(r00, r01, r10, r11);
    }

    // ---- load: float4 global -> padded smem (addr = 33*(i>>3) + 4*(i&7)) ----
    const float4* xc4 = (const float4*)(x + (size_t)c * TLEN + (size_t)seg * SEG);
    for (int i = tid; i < NF4; i += THREADS) {
        float4 v = xc4[i];
        float* p = S->sx + STRIDE * (i >> 3) + ((i & 7) << 2);
        p[0] = v.x; p[1] = v.y; p[2] = v.z; p[3] = v.w;
    }
    __syncthreads();                                        // B1

    // ---- passA: zero-state recurrence, y0 written in place ----
    float z1 = 0.f, z2 = 0.f;
    if (tid < NCH) {
        const float B0 = gb0[c], B1v = gb1[c], B2v = gb2[c];
        float* p = S->sx + tid * STRIDE;
        #pragma unroll
        for (int j = 0; j < CHUNK; j++) {
            float xv = p[j];
            float y  = fmaf(B0, xv, z1);
            float w  = fmaf(B1v, xv, z2);
            z1 = fmaf(-A1, y, w);
            z2 = fmaf(-A2, y, B2v * xv);
            p[j] = y;
        }
    }

    // ---- thread 0: fetch incoming segment state, seed the scan ----
    float sinx = 0.f, siny = 0.f;
    if (tid == 0 && seg > 0) {
        volatile int* fp = g_flag + (bid - 1);
        while (*fp == 0) { }
        __threadfence();
        volatile float* sp = (volatile float*)&g_state[bid - 1];
        sinx = sp[0]; siny = sp[1];
        z1 = fmaf(q00, sinx, fmaf(q01, siny, z1));   // d0 += Q * s_in
        z2 = fmaf(q10, sinx, fmaf(q11, siny, z2));
    }

    // ---- in-warp inclusive affine scan (level matrix Q^(2^l)) ----
    float ex = z1, ey = z2;
    float l00 = q00, l01 = q01, l10 = q10, l11 = q11;
    #pragma unroll
    for (int o = 1; o < 32; o <<= 1) {
        float px = __shfl_up_sync(0xffffffffu, ex, o);
        float py = __shfl_up_sync(0xffffffffu, ey, o);
        if (lane >= o) {
            ex = fmaf(l00, px, fmaf(l01, py, ex));
            ey = fmaf(l10, px, fmaf(l11, py, ey));
        }
        MATSQ(l00,l01,l10,l11);          // exits as Q^32
    }
    if (lane == 31) S->warp_agg[warp] = make_float2(ex, ey);
    __syncthreads();                                        // B2

    // ---- cross-warp scan of 16 aggregates by warp 0 (matrix Q^32) ----
    if (warp == 0) {
        float wx = 0.f, wy = 0.f;
        if (lane < 16) { float2 t = S->warp_agg[lane]; wx = t.x; wy = t.y; }
        #pragma unroll
        for (int o = 1; o < 16; o <<= 1) {
            float px = __shfl_up_sync(0xffffffffu, wx, o);
            float py = __shfl_up_sync(0xffffffffu, wy, o);
            if (lane >= o && lane < 16) {
                wx = fmaf(l00, px, fmaf(l01, py, wx));
                wy = fmaf(l10, px, fmaf(l11, py, wy));
            }
            MATSQ(l00,l01,l10,l11);
        }
        if (lane < 16) S->warp_E[lane] = make_float2(wx, wy);
    }
    __syncthreads();                                        // B3

    // ---- apply cross-warp prefix: e_i += Q^(lane+1) * E_{warp-1} ----
    float Ex = 0.f, Ey = 0.f;
    if (warp > 0) {
        float2 t = S->warp_E[warp - 1]; Ex = t.x; Ey = t.y;
        float4 g = S->gt[lane];
        ex = fmaf(g.x, Ex, fmaf(g.y, Ey, ex));
        ey = fmaf(g.z, Ex, fmaf(g.w, Ey, ey));
    }
    // previous element's true incoming state
    float pex = __shfl_up_sync(0xffffffffu, ex, 1);
    float pey = __shfl_up_sync(0xffffffffu, ey, 1);
    if (lane == 0) { pex = Ex; pey = Ey; }
    if (tid == 0)  { pex = sinx; pey = siny; }

    // ---- publish outgoing segment state (thread NCH-1 holds it) ----
    if (tid == NCH - 1 && seg < NSEG - 1) {
        volatile float* dp = (volatile float*)&g_state[bid];
        dp[0] = ex; dp[1] = ey;
        __threadfence();
        *((volatile int*)(g_flag + bid)) = 1;
    }

    if (tid < 384) S->sv_in[tid] = make_float2(pex, pey);
    __syncthreads();                                        // B4

    // ---- store: y = y0 + row0(M^j) . sv_in[chunk], float4 STG ----
    float4* oc4 = (float4*)(out + (size_t)c * TLEN + (size_t)seg * SEG);
    const float4* mjp = (const float4*)S->mj;
    for (int i = tid; i < NF4; i += THREADS) {
        int ch = i >> 3;
        int b  = i & 7;
        float2 s = S->sv_in[ch];
        const float* p = S->sx + STRIDE * ch + (b << 2);
        float4 r01 = mjp[2 * b];        // mj[4b], mj[4b+1]
        float4 r23 = mjp[2 * b + 1];    // mj[4b+2], mj[4b+3]
        float4 v;
        v.x = fmaf(r01.x, s.x, fmaf(r01.y, s.y, p[0]));
        v.y = fmaf(r01.z, s.x, fmaf(r01.w, s.y, p[1]));
        v.z = fmaf(r23.x, s.x, fmaf(r23.y, s.y, p[2]));
        v.w = fmaf(r23.z, s.x, fmaf(r23.w, s.y, p[3]));
        oc4[i] = v;
    }
}

extern "C" void kernel_launch(void* const* d_in, const int* in_sizes, int n_in,
                              void* d_out, int out_size)
{
    const float* x  = (const float*)d_in[0];
    const float* b0 = (const float*)d_in[1];
    const float* b1 = (const float*)d_in[2];
    const float* b2 = (const float*)d_in[3];
    const float* a1 = (const float*)d_in[4];
    const float* a2 = (const float*)d_in[5];
    float* out = (float*)d_out;

    cudaFuncSetAttribute(biquad_kernel,
                         cudaFuncAttributeMaxDynamicSharedMemorySize,
                         SMEM_BYTES);

    init_flags_kernel<<<NBLK / THREADS, THREADS>>>();
    biquad_kernel<<<NBLK, THREADS, SMEM_BYTES>>>(x, b0, b1, b2, a1, a2, out);
}